// round 1
// baseline (speedup 1.0000x reference)
#include <cuda_runtime.h>
#include <cuda_bf16.h>

#define BB 4
#define SS 1024
#define HH 16
#define HDIM 64
#define DD 1024
#define QT 32

// scratch (device globals — no allocation allowed)
__device__ float g_qkv[BB * SS * 3 * DD];   // [B,S,3D]
__device__ float g_vals[BB * SS * DD];      // [B,S,D] (head-interleaved in D)

// ---------------------------------------------------------------------------
// SGEMM: C[M,N] = A[M,K] @ W[K,N] + bias[N]
// 128x128 block tile, BK=16, 8x8 per-thread, 256 threads
// ---------------------------------------------------------------------------
__global__ __launch_bounds__(256) void sgemm_bias(
    const float* __restrict__ A, const float* __restrict__ W,
    const float* __restrict__ bias, float* __restrict__ C,
    int M, int N, int K)
{
    const int BM = 128, BN = 128, BK = 16;
    __shared__ float As[BK][BM];
    __shared__ float Bs[BK][BN];

    int tid = threadIdx.x;
    int brow = blockIdx.y * BM;
    int bcol = blockIdx.x * BN;
    int ty = tid / 16, tx = tid % 16;
    int m0 = ty * 8, n0 = tx * 8;

    float acc[8][8] = {};

    for (int kt = 0; kt < K; kt += BK) {
        // Load A tile (BMxBK), store transposed As[k][m]
        #pragma unroll
        for (int i = 0; i < 2; i++) {
            int idx = tid + i * 256;        // 0..511
            int row = idx >> 2;             // 0..127
            int k4  = (idx & 3) * 4;        // 0,4,8,12
            float4 v = *(const float4*)&A[(size_t)(brow + row) * K + kt + k4];
            As[k4 + 0][row] = v.x;
            As[k4 + 1][row] = v.y;
            As[k4 + 2][row] = v.z;
            As[k4 + 3][row] = v.w;
        }
        // Load B tile (BKxBN) direct
        #pragma unroll
        for (int i = 0; i < 2; i++) {
            int idx = tid + i * 256;
            int kr = idx >> 5;              // 0..15
            int c4 = (idx & 31) * 4;        // 0..124
            *(float4*)&Bs[kr][c4] = *(const float4*)&W[(size_t)(kt + kr) * N + bcol + c4];
        }
        __syncthreads();

        #pragma unroll
        for (int k = 0; k < BK; k++) {
            float4 a0 = *(const float4*)&As[k][m0];
            float4 a1 = *(const float4*)&As[k][m0 + 4];
            float4 b0 = *(const float4*)&Bs[k][n0];
            float4 b1 = *(const float4*)&Bs[k][n0 + 4];
            float ar[8] = {a0.x, a0.y, a0.z, a0.w, a1.x, a1.y, a1.z, a1.w};
            float br[8] = {b0.x, b0.y, b0.z, b0.w, b1.x, b1.y, b1.z, b1.w};
            #pragma unroll
            for (int i = 0; i < 8; i++)
                #pragma unroll
                for (int j = 0; j < 8; j++)
                    acc[i][j] += ar[i] * br[j];
        }
        __syncthreads();
    }

    #pragma unroll
    for (int i = 0; i < 8; i++) {
        #pragma unroll
        for (int j = 0; j < 8; j += 4) {
            float4 o;
            o.x = acc[i][j + 0] + bias[bcol + n0 + j + 0];
            o.y = acc[i][j + 1] + bias[bcol + n0 + j + 1];
            o.z = acc[i][j + 2] + bias[bcol + n0 + j + 2];
            o.w = acc[i][j + 3] + bias[bcol + n0 + j + 3];
            *(float4*)&C[(size_t)(brow + m0 + i) * N + bcol + n0 + j] = o;
        }
    }
}

// ---------------------------------------------------------------------------
// Fused attention: per block = one (b, h, 32-row q tile)
//   logits tile [32][1024] kept in smem; softmax in smem; attention written to
//   gmem; AV computed from smem P streaming V chunks.
// ---------------------------------------------------------------------------
#define KTP 132   // sKT row stride (64 rows of 128+4)
#define VP  68    // sV row stride (64+4)

__global__ __launch_bounds__(256) void attn_kernel(float* __restrict__ attn_out)
{
    extern __shared__ float sm[];
    float* sP    = sm;                      // [QT][SS]        32768
    float* sQ    = sP  + QT * SS;           // [QT][HDIM]       2048
    float* sKT   = sQ  + QT * HDIM;         // [HDIM][KTP]      8448
    float* sV    = sKT + HDIM * KTP;        // [128][VP]        8704
    float* sStat = sV  + 128 * VP;          // [QT]               32

    const int qt = blockIdx.x, h = blockIdx.y, b = blockIdx.z;
    const int tid = threadIdx.x;
    const int q0 = qt * QT;
    const int ty = tid >> 5, tx = tid & 31;   // warp, lane

    // ---- load Q tile, pre-scaled by 1/sqrt(hd) = 0.125
    for (int i = tid; i < QT * (HDIM / 2); i += 256) {
        int r = i / (HDIM / 2);
        int d2 = (i % (HDIM / 2)) * 2;
        float2 v = *(const float2*)&g_qkv[(size_t)(b * SS + q0 + r) * 3072 + h * 192 + d2];
        sQ[r * HDIM + d2 + 0] = v.x * 0.125f;
        sQ[r * HDIM + d2 + 1] = v.y * 0.125f;
    }

    // ---- GEMM1: S = Q @ K^T  (M=32, N=1024, K=64), N chunks of 128
    for (int kb = 0; kb < SS; kb += 128) {
        __syncthreads();
        // load K chunk transposed: K[kb+row][d] -> sKT[d][row]
        for (int i = tid; i < 128 * 16; i += 256) {
            int row = i >> 4;
            int d4  = (i & 15) * 4;
            float4 v = *(const float4*)&g_qkv[(size_t)(b * SS + kb + row) * 3072 + h * 192 + 64 + d4];
            sKT[(d4 + 0) * KTP + row] = v.x;
            sKT[(d4 + 1) * KTP + row] = v.y;
            sKT[(d4 + 2) * KTP + row] = v.z;
            sKT[(d4 + 3) * KTP + row] = v.w;
        }
        __syncthreads();

        float acc[4][4] = {};
        #pragma unroll 8
        for (int k = 0; k < HDIM; k++) {
            float a0 = sQ[(ty * 4 + 0) * HDIM + k];
            float a1 = sQ[(ty * 4 + 1) * HDIM + k];
            float a2 = sQ[(ty * 4 + 2) * HDIM + k];
            float a3 = sQ[(ty * 4 + 3) * HDIM + k];
            float b0 = sKT[k * KTP + tx];
            float b1 = sKT[k * KTP + 32 + tx];
            float b2 = sKT[k * KTP + 64 + tx];
            float b3 = sKT[k * KTP + 96 + tx];
            acc[0][0] += a0 * b0; acc[0][1] += a0 * b1; acc[0][2] += a0 * b2; acc[0][3] += a0 * b3;
            acc[1][0] += a1 * b0; acc[1][1] += a1 * b1; acc[1][2] += a1 * b2; acc[1][3] += a1 * b3;
            acc[2][0] += a2 * b0; acc[2][1] += a2 * b1; acc[2][2] += a2 * b2; acc[2][3] += a2 * b3;
            acc[3][0] += a3 * b0; acc[3][1] += a3 * b1; acc[3][2] += a3 * b2; acc[3][3] += a3 * b3;
        }
        #pragma unroll
        for (int i = 0; i < 4; i++)
            #pragma unroll
            for (int j = 0; j < 4; j++)
                sP[(ty * 4 + i) * SS + kb + j * 32 + tx] = acc[i][j];
    }
    __syncthreads();

    // ---- softmax per row; write normalized attention to gmem; keep exp in sP
    for (int r = ty; r < QT; r += 8) {
        float* row = &sP[r * SS];
        float m = -1e30f;
        for (int c = tx; c < SS; c += 32) m = fmaxf(m, row[c]);
        #pragma unroll
        for (int o = 16; o > 0; o >>= 1) m = fmaxf(m, __shfl_xor_sync(0xFFFFFFFFu, m, o));
        float sum = 0.f;
        for (int c = tx; c < SS; c += 32) {
            float e = __expf(row[c] - m);
            row[c] = e;
            sum += e;
        }
        #pragma unroll
        for (int o = 16; o > 0; o >>= 1) sum += __shfl_xor_sync(0xFFFFFFFFu, sum, o);
        float inv = 1.0f / sum;
        if (tx == 0) sStat[r] = inv;
        size_t base = ((size_t)((b * HH + h) * SS) + q0 + r) * SS;
        for (int c = tx; c < SS; c += 32) attn_out[base + c] = row[c] * inv;
    }
    __syncthreads();

    // ---- AV: vals[32,64] = P[32,1024] @ V[1024,64] (normalize at end)
    float vacc[4][2] = {};
    for (int kb = 0; kb < SS; kb += 128) {
        __syncthreads();
        for (int i = tid; i < 128 * 16; i += 256) {
            int row = i >> 4;
            int d4  = (i & 15) * 4;
            float4 v = *(const float4*)&g_qkv[(size_t)(b * SS + kb + row) * 3072 + h * 192 + 128 + d4];
            *(float4*)&sV[row * VP + d4] = v;
        }
        __syncthreads();
        #pragma unroll 4
        for (int k = 0; k < 128; k++) {
            float2 vv = *(const float2*)&sV[k * VP + 2 * tx];
            #pragma unroll
            for (int i = 0; i < 4; i++) {
                float p = sP[(ty * 4 + i) * SS + kb + k];
                vacc[i][0] += p * vv.x;
                vacc[i][1] += p * vv.y;
            }
        }
    }

    #pragma unroll
    for (int i = 0; i < 4; i++) {
        int r = ty * 4 + i;
        float inv = sStat[r];
        float2 o;
        o.x = vacc[i][0] * inv;
        o.y = vacc[i][1] * inv;
        *(float2*)&g_vals[(size_t)(b * SS + q0 + r) * DD + h * 64 + 2 * tx] = o;
    }
}

// ---------------------------------------------------------------------------
extern "C" void kernel_launch(void* const* d_in, const int* in_sizes, int n_in,
                              void* d_out, int out_size)
{
    const float* x     = (const float*)d_in[0];
    const float* W_qkv = (const float*)d_in[1];
    const float* b_qkv = (const float*)d_in[2];
    const float* W_o   = (const float*)d_in[3];
    const float* b_o   = (const float*)d_in[4];

    float* out_o    = (float*)d_out;                       // [B,S,D]
    float* out_attn = (float*)d_out + (size_t)BB * SS * DD; // [B,H,S,S]

    float* qkv_ptr = nullptr;
    float* vals_ptr = nullptr;
    cudaGetSymbolAddress((void**)&qkv_ptr, g_qkv);
    cudaGetSymbolAddress((void**)&vals_ptr, g_vals);

    // 1) QKV projection: [4096,1024] @ [1024,3072]
    {
        dim3 grid(3 * DD / 128, BB * SS / 128);
        sgemm_bias<<<grid, 256>>>(x, W_qkv, b_qkv, qkv_ptr, BB * SS, 3 * DD, DD);
    }

    // 2) fused attention
    {
        int smem = (QT * SS + QT * HDIM + HDIM * KTP + 128 * VP + QT) * sizeof(float);
        cudaFuncSetAttribute(attn_kernel, cudaFuncAttributeMaxDynamicSharedMemorySize, smem);
        dim3 grid(SS / QT, HH, BB);
        attn_kernel<<<grid, 256, smem>>>(out_attn);
    }

    // 3) output projection: [4096,1024] @ [1024,1024]
    {
        dim3 grid(DD / 128, BB * SS / 128);
        sgemm_bias<<<grid, 256>>>(vals_ptr, W_o, b_o, out_o, BB * SS, DD, DD);
    }
}

// round 3
// speedup vs baseline: 1.3187x; 1.3187x over previous
#include <cuda_runtime.h>
#include <cuda_bf16.h>

#define BB 4
#define SS 1024
#define HH 16
#define HDIM 64
#define DD 1024
#define QT 32

// ---------------------------------------------------------------------------
// scratch (device globals — no allocation allowed)
// ---------------------------------------------------------------------------
__device__ float g_qkv[BB * SS * 3 * DD];   // [B,S,3D]
__device__ float g_vals[BB * SS * DD];      // [B,S,D]
__device__ __nv_bfloat16 g_xhi[BB * SS * DD];
__device__ __nv_bfloat16 g_xlo[BB * SS * DD];
__device__ __nv_bfloat16 g_wqT_hi[3 * DD * DD];
__device__ __nv_bfloat16 g_wqT_lo[3 * DD * DD];
__device__ __nv_bfloat16 g_woT_hi[DD * DD];
__device__ __nv_bfloat16 g_woT_lo[DD * DD];
__device__ __nv_bfloat16 g_vhi[BB * SS * DD];
__device__ __nv_bfloat16 g_vlo[BB * SS * DD];

// ---------------------------------------------------------------------------
__device__ __forceinline__ unsigned smem_u32(const void* p) {
    unsigned a;
    asm("{ .reg .u64 t; cvta.to.shared.u64 t, %1; cvt.u32.u64 %0, t; }" : "=r"(a) : "l"(p));
    return a;
}
#define SWZ128(o) ((o) ^ (((o) >> 3) & 0x70))

#define CP_ASYNC16(saddr, gptr) \
    asm volatile("cp.async.cg.shared.global [%0], [%1], 16;" :: "r"(saddr), "l"(gptr) : "memory")
#define CP_COMMIT() asm volatile("cp.async.commit_group;" ::: "memory")
#define CP_WAIT1()  asm volatile("cp.async.wait_group 1;" ::: "memory")
#define CP_WAIT0()  asm volatile("cp.async.wait_group 0;" ::: "memory")

#define LDMX4(r0, r1, r2, r3, a) \
    asm volatile("ldmatrix.sync.aligned.m8n8.x4.shared.b16 {%0,%1,%2,%3}, [%4];" \
        : "=r"(r0), "=r"(r1), "=r"(r2), "=r"(r3) : "r"(a))

#define MMA16816(d, a, b0, b1) \
    asm volatile("mma.sync.aligned.m16n8k16.row.col.f32.bf16.bf16.f32 " \
        "{%0,%1,%2,%3}, {%4,%5,%6,%7}, {%8,%9}, {%0,%1,%2,%3};" \
        : "+f"((d)[0]), "+f"((d)[1]), "+f"((d)[2]), "+f"((d)[3]) \
        : "r"((a)[0]), "r"((a)[1]), "r"((a)[2]), "r"((a)[3]), "r"(b0), "r"(b1))

// ---------------------------------------------------------------------------
// split: fp32 -> (hi, lo) bf16, elementwise
// ---------------------------------------------------------------------------
__global__ __launch_bounds__(256) void split_kernel(
    const float* __restrict__ src, __nv_bfloat16* __restrict__ hi,
    __nv_bfloat16* __restrict__ lo, int n4)
{
    int i = blockIdx.x * 256 + threadIdx.x;
    if (i >= n4) return;
    float4 v = ((const float4*)src)[i];
    float vv[4] = {v.x, v.y, v.z, v.w};
    __nv_bfloat16 h[4], l[4];
    #pragma unroll
    for (int j = 0; j < 4; j++) {
        h[j] = __float2bfloat16(vv[j]);
        l[j] = __float2bfloat16(vv[j] - __bfloat162float(h[j]));
    }
    ((ushort4*)hi)[i] = make_ushort4(__bfloat16_as_ushort(h[0]), __bfloat16_as_ushort(h[1]),
                                     __bfloat16_as_ushort(h[2]), __bfloat16_as_ushort(h[3]));
    ((ushort4*)lo)[i] = make_ushort4(__bfloat16_as_ushort(l[0]), __bfloat16_as_ushort(l[1]),
                                     __bfloat16_as_ushort(l[2]), __bfloat16_as_ushort(l[3]));
}

// ---------------------------------------------------------------------------
// transpose+split: W[K,N] fp32 -> hiT/loT [N,K] bf16
// ---------------------------------------------------------------------------
__global__ __launch_bounds__(256) void tsplit_kernel(
    const float* __restrict__ W, __nv_bfloat16* __restrict__ hiT,
    __nv_bfloat16* __restrict__ loT, int K, int N)
{
    __shared__ float t[32][33];
    int k0 = blockIdx.y * 32, n0 = blockIdx.x * 32;
    int tx = threadIdx.x, ty = threadIdx.y;  // (32,8)
    #pragma unroll
    for (int i = 0; i < 32; i += 8)
        t[ty + i][tx] = W[(size_t)(k0 + ty + i) * N + n0 + tx];
    __syncthreads();
    #pragma unroll
    for (int i = 0; i < 32; i += 8) {
        float v = t[tx][ty + i];
        __nv_bfloat16 h = __float2bfloat16(v);
        size_t o = (size_t)(n0 + ty + i) * K + k0 + tx;
        hiT[o] = h;
        loT[o] = __float2bfloat16(v - __bfloat162float(h));
    }
}

// ---------------------------------------------------------------------------
// mma.sync GEMM, 3xBF16 split: C[M,N] = Ahi@BThi^T + Alo@BThi^T + Ahi@BTlo^T + bias
// 128x128 block, 8 warps (64x32 each), K-chunk 64, double-buffered cp.async.
// smem tiles: [128 rows][64 cols bf16] = 128B/row, SW128 swizzled.
// ---------------------------------------------------------------------------
#define GT_A0 0
#define GT_A1 16384
#define GT_B0 32768
#define GT_B1 49152
#define GT_TOTAL 65536

__device__ __forceinline__ void prefetch_tile(
    const __nv_bfloat16* __restrict__ A, const __nv_bfloat16* __restrict__ BT,
    int brow, int bcol, int K, int kt,
    unsigned sa, unsigned sbB, int tid)
{
    #pragma unroll
    for (int i = 0; i < 4; i++) {
        int idx = tid + i * 256;           // 0..1023
        int row = idx >> 3;                // 0..127
        int c16 = (idx & 7) * 16;          // byte col 0..112
        unsigned soff = SWZ128((unsigned)(row * 128 + c16));
        CP_ASYNC16(sa + soff, (const char*)(A + (size_t)(brow + row) * K + kt) + c16);
    }
    #pragma unroll
    for (int i = 0; i < 4; i++) {
        int idx = tid + i * 256;
        int row = idx >> 3;
        int c16 = (idx & 7) * 16;
        unsigned soff = SWZ128((unsigned)(row * 128 + c16));
        CP_ASYNC16(sbB + soff, (const char*)(BT + (size_t)(bcol + row) * K + kt) + c16);
    }
}

__global__ __launch_bounds__(256) void gemm3x_mma(
    const __nv_bfloat16* __restrict__ Ahi, const __nv_bfloat16* __restrict__ Alo,
    const __nv_bfloat16* __restrict__ BThi, const __nv_bfloat16* __restrict__ BTlo,
    const float* __restrict__ bias, float* __restrict__ C,
    int M, int N, int K)
{
    extern __shared__ char smem[];
    unsigned sb = smem_u32(smem);
    const int tid = threadIdx.x, w = tid >> 5, lane = tid & 31;
    const int brow = blockIdx.y * 128, bcol = blockIdx.x * 128;

    const __nv_bfloat16* Ap[3] = {Ahi, Alo, Ahi};
    const __nv_bfloat16* Bp[3] = {BThi, BThi, BTlo};
    unsigned saA[2] = {sb + GT_A0, sb + GT_A1};
    unsigned saB[2] = {sb + GT_B0, sb + GT_B1};

    const int nk = K >> 6;          // chunks per pass
    const int nch = 3 * nk;

    // per-warp tile origin
    const int wm = (w >> 2) * 64;   // 0 or 64
    const int wn = (w & 3) * 32;    // 0,32,64,96

    // ldmatrix lane addressing constants
    const int lrow = lane & 15;
    const int lcolB = (lane >> 4) * 16;   // byte offset within row

    float acc[4][4][4] = {};

    // prologue: prefetch chunks 0,1
    prefetch_tile(Ap[0], Bp[0], brow, bcol, K, 0, saA[0], saB[0], tid);
    CP_COMMIT();
    if (nch > 1) {
        prefetch_tile(Ap[1 / nk], Bp[1 / nk], brow, bcol, K, (1 % nk) << 6,
                      saA[1], saB[1], tid);
        CP_COMMIT();
    }

    for (int c = 0; c < nch; c++) {
        if (c + 1 < nch) CP_WAIT1(); else CP_WAIT0();
        __syncthreads();

        int buf = c & 1;
        unsigned baseA = saA[buf], baseB = saB[buf];

        #pragma unroll
        for (int ks = 0; ks < 4; ks++) {
            int kb = ks * 32;  // byte offset of k16 step
            unsigned afr[4][4];
            unsigned bfr[2][4];
            #pragma unroll
            for (int i = 0; i < 4; i++) {
                unsigned off = (unsigned)((wm + i * 16 + lrow) * 128 + kb + lcolB);
                unsigned ad = baseA + SWZ128(off);
                LDMX4(afr[i][0], afr[i][1], afr[i][2], afr[i][3], ad);
            }
            #pragma unroll
            for (int j2 = 0; j2 < 2; j2++) {
                unsigned off = (unsigned)((wn + j2 * 16 + lrow) * 128 + kb + lcolB);
                unsigned ad = baseB + SWZ128(off);
                LDMX4(bfr[j2][0], bfr[j2][1], bfr[j2][2], bfr[j2][3], ad);
            }
            #pragma unroll
            for (int i = 0; i < 4; i++) {
                #pragma unroll
                for (int j = 0; j < 4; j++) {
                    unsigned b0 = (j & 1) ? bfr[j >> 1][1] : bfr[j >> 1][0];
                    unsigned b1 = (j & 1) ? bfr[j >> 1][3] : bfr[j >> 1][2];
                    MMA16816(acc[i][j], afr[i], b0, b1);
                }
            }
        }
        __syncthreads();

        if (c + 2 < nch) {
            int cn = c + 2;
            int p = cn / nk, kt = (cn - p * nk) << 6;
            prefetch_tile(Ap[p], Bp[p], brow, bcol, K, kt, saA[buf], saB[buf], tid);
            CP_COMMIT();
        }
    }

    // epilogue: acc layout: rows (lane>>2) & +8, cols (lane&3)*2
    const int r0 = brow + wm + (lane >> 2);
    const int c0 = bcol + wn + (lane & 3) * 2;
    #pragma unroll
    for (int i = 0; i < 4; i++) {
        #pragma unroll
        for (int j = 0; j < 4; j++) {
            int col = c0 + j * 8;
            float bx = bias[col], by = bias[col + 1];
            float2 o0 = make_float2(acc[i][j][0] + bx, acc[i][j][1] + by);
            float2 o1 = make_float2(acc[i][j][2] + bx, acc[i][j][3] + by);
            *(float2*)&C[(size_t)(r0 + i * 16) * N + col] = o0;
            *(float2*)&C[(size_t)(r0 + i * 16 + 8) * N + col] = o1;
        }
    }
}

// ---------------------------------------------------------------------------
// Fused attention (unchanged from R1 — known good)
// ---------------------------------------------------------------------------
#define KTP 132
#define VP  68

__global__ __launch_bounds__(256) void attn_kernel(float* __restrict__ attn_out)
{
    extern __shared__ float sm[];
    float* sP    = sm;
    float* sQ    = sP  + QT * SS;
    float* sKT   = sQ  + QT * HDIM;
    float* sV    = sKT + HDIM * KTP;
    float* sStat = sV  + 128 * VP;

    const int qt = blockIdx.x, h = blockIdx.y, b = blockIdx.z;
    const int tid = threadIdx.x;
    const int q0 = qt * QT;
    const int ty = tid >> 5, tx = tid & 31;

    for (int i = tid; i < QT * (HDIM / 2); i += 256) {
        int r = i / (HDIM / 2);
        int d2 = (i % (HDIM / 2)) * 2;
        float2 v = *(const float2*)&g_qkv[(size_t)(b * SS + q0 + r) * 3072 + h * 192 + d2];
        sQ[r * HDIM + d2 + 0] = v.x * 0.125f;
        sQ[r * HDIM + d2 + 1] = v.y * 0.125f;
    }

    for (int kb = 0; kb < SS; kb += 128) {
        __syncthreads();
        for (int i = tid; i < 128 * 16; i += 256) {
            int row = i >> 4;
            int d4  = (i & 15) * 4;
            float4 v = *(const float4*)&g_qkv[(size_t)(b * SS + kb + row) * 3072 + h * 192 + 64 + d4];
            sKT[(d4 + 0) * KTP + row] = v.x;
            sKT[(d4 + 1) * KTP + row] = v.y;
            sKT[(d4 + 2) * KTP + row] = v.z;
            sKT[(d4 + 3) * KTP + row] = v.w;
        }
        __syncthreads();

        float acc[4][4] = {};
        #pragma unroll 8
        for (int k = 0; k < HDIM; k++) {
            float a0 = sQ[(ty * 4 + 0) * HDIM + k];
            float a1 = sQ[(ty * 4 + 1) * HDIM + k];
            float a2 = sQ[(ty * 4 + 2) * HDIM + k];
            float a3 = sQ[(ty * 4 + 3) * HDIM + k];
            float b0 = sKT[k * KTP + tx];
            float b1 = sKT[k * KTP + 32 + tx];
            float b2 = sKT[k * KTP + 64 + tx];
            float b3 = sKT[k * KTP + 96 + tx];
            acc[0][0] += a0 * b0; acc[0][1] += a0 * b1; acc[0][2] += a0 * b2; acc[0][3] += a0 * b3;
            acc[1][0] += a1 * b0; acc[1][1] += a1 * b1; acc[1][2] += a1 * b2; acc[1][3] += a1 * b3;
            acc[2][0] += a2 * b0; acc[2][1] += a2 * b1; acc[2][2] += a2 * b2; acc[2][3] += a2 * b3;
            acc[3][0] += a3 * b0; acc[3][1] += a3 * b1; acc[3][2] += a3 * b2; acc[3][3] += a3 * b3;
        }
        #pragma unroll
        for (int i = 0; i < 4; i++)
            #pragma unroll
            for (int j = 0; j < 4; j++)
                sP[(ty * 4 + i) * SS + kb + j * 32 + tx] = acc[i][j];
    }
    __syncthreads();

    for (int r = ty; r < QT; r += 8) {
        float* row = &sP[r * SS];
        float m = -1e30f;
        for (int c = tx; c < SS; c += 32) m = fmaxf(m, row[c]);
        #pragma unroll
        for (int o = 16; o > 0; o >>= 1) m = fmaxf(m, __shfl_xor_sync(0xFFFFFFFFu, m, o));
        float sum = 0.f;
        for (int c = tx; c < SS; c += 32) {
            float e = __expf(row[c] - m);
            row[c] = e;
            sum += e;
        }
        #pragma unroll
        for (int o = 16; o > 0; o >>= 1) sum += __shfl_xor_sync(0xFFFFFFFFu, sum, o);
        float inv = 1.0f / sum;
        if (tx == 0) sStat[r] = inv;
        size_t base = ((size_t)((b * HH + h) * SS) + q0 + r) * SS;
        for (int c = tx; c < SS; c += 32) attn_out[base + c] = row[c] * inv;
    }
    __syncthreads();

    float vacc[4][2] = {};
    for (int kb = 0; kb < SS; kb += 128) {
        __syncthreads();
        for (int i = tid; i < 128 * 16; i += 256) {
            int row = i >> 4;
            int d4  = (i & 15) * 4;
            float4 v = *(const float4*)&g_qkv[(size_t)(b * SS + kb + row) * 3072 + h * 192 + 128 + d4];
            *(float4*)&sV[row * VP + d4] = v;
        }
        __syncthreads();
        #pragma unroll 4
        for (int k = 0; k < 128; k++) {
            float2 vv = *(const float2*)&sV[k * VP + 2 * tx];
            #pragma unroll
            for (int i = 0; i < 4; i++) {
                float p = sP[(ty * 4 + i) * SS + kb + k];
                vacc[i][0] += p * vv.x;
                vacc[i][1] += p * vv.y;
            }
        }
    }

    #pragma unroll
    for (int i = 0; i < 4; i++) {
        int r = ty * 4 + i;
        float inv = sStat[r];
        float2 o;
        o.x = vacc[i][0] * inv;
        o.y = vacc[i][1] * inv;
        *(float2*)&g_vals[(size_t)(b * SS + q0 + r) * DD + h * 64 + 2 * tx] = o;
    }
}

// ---------------------------------------------------------------------------
extern "C" void kernel_launch(void* const* d_in, const int* in_sizes, int n_in,
                              void* d_out, int out_size)
{
    const float* x     = (const float*)d_in[0];
    const float* W_qkv = (const float*)d_in[1];
    const float* b_qkv = (const float*)d_in[2];
    const float* W_o   = (const float*)d_in[3];
    const float* b_o   = (const float*)d_in[4];

    float* out_o    = (float*)d_out;
    float* out_attn = (float*)d_out + (size_t)BB * SS * DD;

    float *qkv_ptr, *vals_ptr;
    __nv_bfloat16 *xhi, *xlo, *wqh, *wql, *woh, *wol, *vhi, *vlo;
    cudaGetSymbolAddress((void**)&qkv_ptr, g_qkv);
    cudaGetSymbolAddress((void**)&vals_ptr, g_vals);
    cudaGetSymbolAddress((void**)&xhi, g_xhi);
    cudaGetSymbolAddress((void**)&xlo, g_xlo);
    cudaGetSymbolAddress((void**)&wqh, g_wqT_hi);
    cudaGetSymbolAddress((void**)&wql, g_wqT_lo);
    cudaGetSymbolAddress((void**)&woh, g_woT_hi);
    cudaGetSymbolAddress((void**)&wol, g_woT_lo);
    cudaGetSymbolAddress((void**)&vhi, g_vhi);
    cudaGetSymbolAddress((void**)&vlo, g_vlo);

    cudaFuncSetAttribute(gemm3x_mma, cudaFuncAttributeMaxDynamicSharedMemorySize, GT_TOTAL);

    // 0) prep: split x, transpose+split weights
    {
        int n4 = BB * SS * DD / 4;
        split_kernel<<<(n4 + 255) / 256, 256>>>(x, xhi, xlo, n4);
        dim3 g1(3 * DD / 32, DD / 32);
        tsplit_kernel<<<g1, dim3(32, 8)>>>(W_qkv, wqh, wql, DD, 3 * DD);
        dim3 g2(DD / 32, DD / 32);
        tsplit_kernel<<<g2, dim3(32, 8)>>>(W_o, woh, wol, DD, DD);
    }

    // 1) QKV projection via tensor cores
    {
        dim3 grid(3 * DD / 128, BB * SS / 128);
        gemm3x_mma<<<grid, 256, GT_TOTAL>>>(xhi, xlo, wqh, wql, b_qkv, qkv_ptr,
                                            BB * SS, 3 * DD, DD);
    }

    // 2) fused attention
    {
        int smem = (QT * SS + QT * HDIM + HDIM * KTP + 128 * VP + QT) * sizeof(float);
        cudaFuncSetAttribute(attn_kernel, cudaFuncAttributeMaxDynamicSharedMemorySize, smem);
        dim3 grid(SS / QT, HH, BB);
        attn_kernel<<<grid, 256, smem>>>(out_attn);
    }

    // 3) split vals, then O-proj via tensor cores
    {
        int n4 = BB * SS * DD / 4;
        split_kernel<<<(n4 + 255) / 256, 256>>>(vals_ptr, vhi, vlo, n4);
        dim3 grid(DD / 128, BB * SS / 128);
        gemm3x_mma<<<grid, 256, GT_TOTAL>>>(vhi, vlo, woh, wol, b_o, out_o,
                                            BB * SS, DD, DD);
    }
}

// round 4
// speedup vs baseline: 2.6498x; 2.0094x over previous
#include <cuda_runtime.h>
#include <cuda_bf16.h>

#define BB 4
#define SS 1024
#define HH 16
#define HDIM 64
#define DD 1024

// ---------------------------------------------------------------------------
// scratch (device globals — no allocation allowed)
// ---------------------------------------------------------------------------
__device__ float g_qkv[BB * SS * 3 * DD];   // [B,S,3D]
__device__ float g_vals[BB * SS * DD];      // [B,S,D]
__device__ __nv_bfloat16 g_xhi[BB * SS * DD];
__device__ __nv_bfloat16 g_xlo[BB * SS * DD];
__device__ __nv_bfloat16 g_wqT_hi[3 * DD * DD];
__device__ __nv_bfloat16 g_wqT_lo[3 * DD * DD];
__device__ __nv_bfloat16 g_woT_hi[DD * DD];
__device__ __nv_bfloat16 g_woT_lo[DD * DD];
__device__ __nv_bfloat16 g_vhi[BB * SS * DD];
__device__ __nv_bfloat16 g_vlo[BB * SS * DD];
__device__ __nv_bfloat16 g_qh[BB * SS * 3 * DD];   // qkv split hi
__device__ __nv_bfloat16 g_ql[BB * SS * 3 * DD];   // qkv split lo
__device__ __nv_bfloat16 g_vTh[BB * HH * HDIM * SS]; // V^T per (b,h): [64][S]
__device__ __nv_bfloat16 g_vTl[BB * HH * HDIM * SS];

// ---------------------------------------------------------------------------
__device__ __forceinline__ unsigned smem_u32(const void* p) {
    unsigned a;
    asm("{ .reg .u64 t; cvta.to.shared.u64 t, %1; cvt.u32.u64 %0, t; }" : "=r"(a) : "l"(p));
    return a;
}
#define SWZ128(o) ((o) ^ (((o) >> 3) & 0x70))

#define CP_ASYNC16(saddr, gptr) \
    asm volatile("cp.async.cg.shared.global [%0], [%1], 16;" :: "r"(saddr), "l"(gptr) : "memory")
#define CP_COMMIT() asm volatile("cp.async.commit_group;" ::: "memory")
#define CP_WAIT1()  asm volatile("cp.async.wait_group 1;" ::: "memory")
#define CP_WAIT0()  asm volatile("cp.async.wait_group 0;" ::: "memory")

#define LDMX4(r0, r1, r2, r3, a) \
    asm volatile("ldmatrix.sync.aligned.m8n8.x4.shared.b16 {%0,%1,%2,%3}, [%4];" \
        : "=r"(r0), "=r"(r1), "=r"(r2), "=r"(r3) : "r"(a))

#define MMA16816(d, a, b0, b1) \
    asm volatile("mma.sync.aligned.m16n8k16.row.col.f32.bf16.bf16.f32 " \
        "{%0,%1,%2,%3}, {%4,%5,%6,%7}, {%8,%9}, {%0,%1,%2,%3};" \
        : "+f"((d)[0]), "+f"((d)[1]), "+f"((d)[2]), "+f"((d)[3]) \
        : "r"((a)[0]), "r"((a)[1]), "r"((a)[2]), "r"((a)[3]), "r"(b0), "r"(b1))

// ---------------------------------------------------------------------------
__global__ __launch_bounds__(256) void split_kernel(
    const float* __restrict__ src, __nv_bfloat16* __restrict__ hi,
    __nv_bfloat16* __restrict__ lo, int n4)
{
    int i = blockIdx.x * 256 + threadIdx.x;
    if (i >= n4) return;
    float4 v = ((const float4*)src)[i];
    float vv[4] = {v.x, v.y, v.z, v.w};
    __nv_bfloat16 h[4], l[4];
    #pragma unroll
    for (int j = 0; j < 4; j++) {
        h[j] = __float2bfloat16(vv[j]);
        l[j] = __float2bfloat16(vv[j] - __bfloat162float(h[j]));
    }
    ((ushort4*)hi)[i] = make_ushort4(__bfloat16_as_ushort(h[0]), __bfloat16_as_ushort(h[1]),
                                     __bfloat16_as_ushort(h[2]), __bfloat16_as_ushort(h[3]));
    ((ushort4*)lo)[i] = make_ushort4(__bfloat16_as_ushort(l[0]), __bfloat16_as_ushort(l[1]),
                                     __bfloat16_as_ushort(l[2]), __bfloat16_as_ushort(l[3]));
}

__global__ __launch_bounds__(256) void tsplit_kernel(
    const float* __restrict__ W, __nv_bfloat16* __restrict__ hiT,
    __nv_bfloat16* __restrict__ loT, int K, int N)
{
    __shared__ float t[32][33];
    int k0 = blockIdx.y * 32, n0 = blockIdx.x * 32;
    int tx = threadIdx.x, ty = threadIdx.y;
    #pragma unroll
    for (int i = 0; i < 32; i += 8)
        t[ty + i][tx] = W[(size_t)(k0 + ty + i) * N + n0 + tx];
    __syncthreads();
    #pragma unroll
    for (int i = 0; i < 32; i += 8) {
        float v = t[tx][ty + i];
        __nv_bfloat16 h = __float2bfloat16(v);
        size_t o = (size_t)(n0 + ty + i) * K + k0 + tx;
        hiT[o] = h;
        loT[o] = __float2bfloat16(v - __bfloat162float(h));
    }
}

// V^T + split: qkv V slice -> vT hi/lo [bh][64][S]
__global__ __launch_bounds__(256) void vT_kernel(
    const float* __restrict__ qkv, __nv_bfloat16* __restrict__ vTh,
    __nv_bfloat16* __restrict__ vTl)
{
    __shared__ float t[32][33];
    int s0 = blockIdx.x * 32, d0 = blockIdx.y * 32, bh = blockIdx.z;
    int b = bh >> 4, h = bh & 15;
    int tx = threadIdx.x, ty = threadIdx.y;
    #pragma unroll
    for (int i = 0; i < 32; i += 8)
        t[ty + i][tx] = qkv[(size_t)(b * SS + s0 + ty + i) * 3072 + h * 192 + 128 + d0 + tx];
    __syncthreads();
    #pragma unroll
    for (int i = 0; i < 32; i += 8) {
        float v = t[tx][ty + i];
        __nv_bfloat16 hh = __float2bfloat16(v);
        size_t o = (size_t)(bh * HDIM + d0 + ty + i) * SS + s0 + tx;
        vTh[o] = hh;
        vTl[o] = __float2bfloat16(v - __bfloat162float(hh));
    }
}

// ---------------------------------------------------------------------------
// mma.sync GEMM, 3xBF16 split (unchanged from R3)
// ---------------------------------------------------------------------------
#define GT_A0 0
#define GT_A1 16384
#define GT_B0 32768
#define GT_B1 49152
#define GT_TOTAL 65536

__device__ __forceinline__ void prefetch_tile(
    const __nv_bfloat16* __restrict__ A, const __nv_bfloat16* __restrict__ BT,
    int brow, int bcol, int K, int kt,
    unsigned sa, unsigned sbB, int tid)
{
    #pragma unroll
    for (int i = 0; i < 4; i++) {
        int idx = tid + i * 256;
        int row = idx >> 3;
        int c16 = (idx & 7) * 16;
        unsigned soff = SWZ128((unsigned)(row * 128 + c16));
        CP_ASYNC16(sa + soff, (const char*)(A + (size_t)(brow + row) * K + kt) + c16);
    }
    #pragma unroll
    for (int i = 0; i < 4; i++) {
        int idx = tid + i * 256;
        int row = idx >> 3;
        int c16 = (idx & 7) * 16;
        unsigned soff = SWZ128((unsigned)(row * 128 + c16));
        CP_ASYNC16(sbB + soff, (const char*)(BT + (size_t)(bcol + row) * K + kt) + c16);
    }
}

__global__ __launch_bounds__(256) void gemm3x_mma(
    const __nv_bfloat16* __restrict__ Ahi, const __nv_bfloat16* __restrict__ Alo,
    const __nv_bfloat16* __restrict__ BThi, const __nv_bfloat16* __restrict__ BTlo,
    const float* __restrict__ bias, float* __restrict__ C,
    int M, int N, int K)
{
    extern __shared__ char smem[];
    unsigned sb = smem_u32(smem);
    const int tid = threadIdx.x, w = tid >> 5, lane = tid & 31;
    const int brow = blockIdx.y * 128, bcol = blockIdx.x * 128;

    const __nv_bfloat16* Ap[3] = {Ahi, Alo, Ahi};
    const __nv_bfloat16* Bp[3] = {BThi, BThi, BTlo};
    unsigned saA[2] = {sb + GT_A0, sb + GT_A1};
    unsigned saB[2] = {sb + GT_B0, sb + GT_B1};

    const int nk = K >> 6;
    const int nch = 3 * nk;
    const int wm = (w >> 2) * 64;
    const int wn = (w & 3) * 32;
    const int lrow = lane & 15;
    const int lcolB = (lane >> 4) * 16;

    float acc[4][4][4] = {};

    prefetch_tile(Ap[0], Bp[0], brow, bcol, K, 0, saA[0], saB[0], tid);
    CP_COMMIT();
    if (nch > 1) {
        prefetch_tile(Ap[1 / nk], Bp[1 / nk], brow, bcol, K, (1 % nk) << 6,
                      saA[1], saB[1], tid);
        CP_COMMIT();
    }

    for (int c = 0; c < nch; c++) {
        if (c + 1 < nch) CP_WAIT1(); else CP_WAIT0();
        __syncthreads();

        int buf = c & 1;
        unsigned baseA = saA[buf], baseB = saB[buf];

        #pragma unroll
        for (int ks = 0; ks < 4; ks++) {
            int kb = ks * 32;
            unsigned afr[4][4];
            unsigned bfr[2][4];
            #pragma unroll
            for (int i = 0; i < 4; i++) {
                unsigned off = (unsigned)((wm + i * 16 + lrow) * 128 + kb + lcolB);
                LDMX4(afr[i][0], afr[i][1], afr[i][2], afr[i][3], baseA + SWZ128(off));
            }
            #pragma unroll
            for (int j2 = 0; j2 < 2; j2++) {
                unsigned off = (unsigned)((wn + j2 * 16 + lrow) * 128 + kb + lcolB);
                LDMX4(bfr[j2][0], bfr[j2][1], bfr[j2][2], bfr[j2][3], baseB + SWZ128(off));
            }
            #pragma unroll
            for (int i = 0; i < 4; i++) {
                #pragma unroll
                for (int j = 0; j < 4; j++) {
                    unsigned b0 = (j & 1) ? bfr[j >> 1][1] : bfr[j >> 1][0];
                    unsigned b1 = (j & 1) ? bfr[j >> 1][3] : bfr[j >> 1][2];
                    MMA16816(acc[i][j], afr[i], b0, b1);
                }
            }
        }
        __syncthreads();

        if (c + 2 < nch) {
            int cn = c + 2;
            int p = cn / nk, kt = (cn - p * nk) << 6;
            prefetch_tile(Ap[p], Bp[p], brow, bcol, K, kt, saA[buf], saB[buf], tid);
            CP_COMMIT();
        }
    }

    const int r0 = brow + wm + (lane >> 2);
    const int c0 = bcol + wn + (lane & 3) * 2;
    #pragma unroll
    for (int i = 0; i < 4; i++) {
        #pragma unroll
        for (int j = 0; j < 4; j++) {
            int col = c0 + j * 8;
            float bx = bias[col], by = bias[col + 1];
            float2 o0 = make_float2(acc[i][j][0] + bx, acc[i][j][1] + by);
            float2 o1 = make_float2(acc[i][j][2] + bx, acc[i][j][3] + by);
            *(float2*)&C[(size_t)(r0 + i * 16) * N + col] = o0;
            *(float2*)&C[(size_t)(r0 + i * 16 + 8) * N + col] = o1;
        }
    }
}

// ---------------------------------------------------------------------------
// Tensorized fused attention.
// Block = (b, h, 32 q-rows). smem: P fp32 [32][1024], Q hi/lo, K/V chunk bufs.
// QK^T: A=Q, BT=K rows. AV: A=P(split), BT=VT rows. 3 passes each.
// ---------------------------------------------------------------------------
#define AT_P    0
#define AT_QH   131072
#define AT_QL   135168
#define AT_K0   139264     // 2 buffers x 32768 (K: hi16K+lo16K / V: hi8K+lo8K)
#define AT_PH   204800
#define AT_PL   208896
#define AT_TOTAL 212992

__device__ __forceinline__ void attn_load_k(
    const __nv_bfloat16* __restrict__ qh, const __nv_bfloat16* __restrict__ ql,
    int b, int h, int kb, unsigned dstH, unsigned dstL, int tid)
{
    #pragma unroll
    for (int i = 0; i < 4; i++) {
        int idx = tid + i * 256;
        int row = idx >> 3, c16 = (idx & 7) * 16;
        unsigned so = SWZ128((unsigned)(row * 128 + c16));
        CP_ASYNC16(dstH + so, (const char*)(qh + (size_t)(b * SS + kb + row) * 3072 + h * 192 + 64) + c16);
        CP_ASYNC16(dstL + so, (const char*)(ql + (size_t)(b * SS + kb + row) * 3072 + h * 192 + 64) + c16);
    }
}

__device__ __forceinline__ void attn_load_v(
    const __nv_bfloat16* __restrict__ vTh, const __nv_bfloat16* __restrict__ vTl,
    int bh, int kb, unsigned dstH, unsigned dstL, int tid)
{
    #pragma unroll
    for (int i = 0; i < 2; i++) {
        int idx = tid + i * 256;
        int row = idx >> 3, c16 = (idx & 7) * 16;
        unsigned so = SWZ128((unsigned)(row * 128 + c16));
        CP_ASYNC16(dstH + so, (const char*)(vTh + (size_t)(bh * HDIM + row) * SS + kb) + c16);
        CP_ASYNC16(dstL + so, (const char*)(vTl + (size_t)(bh * HDIM + row) * SS + kb) + c16);
    }
}

__global__ __launch_bounds__(256) void attn_mma(
    const __nv_bfloat16* __restrict__ qh, const __nv_bfloat16* __restrict__ ql,
    const __nv_bfloat16* __restrict__ vTh, const __nv_bfloat16* __restrict__ vTl,
    float* __restrict__ attn_out)
{
    extern __shared__ char smem[];
    unsigned sb = smem_u32(smem);
    float* sP = (float*)smem;

    const int qt = blockIdx.x, h = blockIdx.y, b = blockIdx.z;
    const int bh = b * HH + h;
    const int q0 = qt * 32;
    const int tid = threadIdx.x, w = tid >> 5, lane = tid & 31;
    const int lrow = lane & 15, lcol = (lane >> 4) * 16;

    // ---- prologue: Q tile + K chunks 0,1
    {
        int row = tid >> 3, c16 = (tid & 7) * 16;
        unsigned so = SWZ128((unsigned)(row * 128 + c16));
        CP_ASYNC16(sb + AT_QH + so, (const char*)(qh + (size_t)(b * SS + q0 + row) * 3072 + h * 192) + c16);
        CP_ASYNC16(sb + AT_QL + so, (const char*)(ql + (size_t)(b * SS + q0 + row) * 3072 + h * 192) + c16);
    }
    attn_load_k(qh, ql, b, h, 0, sb + AT_K0, sb + AT_K0 + 16384, tid);
    CP_COMMIT();
    attn_load_k(qh, ql, b, h, 128, sb + AT_K0 + 32768, sb + AT_K0 + 49152, tid);
    CP_COMMIT();

    // ---- phase 1: logits = 0.125 * Q K^T  (8 chunks of 128 keys)
    const int wm = (w >> 2) * 16;
    const int wn = (w & 3) * 32;
    for (int c = 0; c < 8; c++) {
        if (c + 1 < 8) CP_WAIT1(); else CP_WAIT0();
        __syncthreads();

        unsigned bufH = sb + AT_K0 + (c & 1) * 32768;
        unsigned bufL = bufH + 16384;
        float acc[4][4] = {};
        #pragma unroll
        for (int p = 0; p < 3; p++) {
            unsigned aBase = sb + (p == 1 ? AT_QL : AT_QH);
            unsigned bBase = (p == 2) ? bufL : bufH;
            #pragma unroll
            for (int ks = 0; ks < 4; ks++) {
                int kb = ks * 32;
                unsigned afr[4];
                LDMX4(afr[0], afr[1], afr[2], afr[3],
                      aBase + SWZ128((unsigned)((wm + lrow) * 128 + kb + lcol)));
                unsigned bfr[2][4];
                #pragma unroll
                for (int j2 = 0; j2 < 2; j2++)
                    LDMX4(bfr[j2][0], bfr[j2][1], bfr[j2][2], bfr[j2][3],
                          bBase + SWZ128((unsigned)((wn + j2 * 16 + lrow) * 128 + kb + lcol)));
                #pragma unroll
                for (int j = 0; j < 4; j++) {
                    unsigned b0 = (j & 1) ? bfr[j >> 1][1] : bfr[j >> 1][0];
                    unsigned b1 = (j & 1) ? bfr[j >> 1][3] : bfr[j >> 1][2];
                    MMA16816(acc[j], afr, b0, b1);
                }
            }
        }
        int r0 = wm + (lane >> 2);
        int cb = c * 128 + wn + (lane & 3) * 2;
        #pragma unroll
        for (int j = 0; j < 4; j++) {
            int col = cb + j * 8;
            *(float2*)&sP[r0 * SS + col]       = make_float2(acc[j][0] * 0.125f, acc[j][1] * 0.125f);
            *(float2*)&sP[(r0 + 8) * SS + col] = make_float2(acc[j][2] * 0.125f, acc[j][3] * 0.125f);
        }
        __syncthreads();
        if (c + 2 < 8) {
            attn_load_k(qh, ql, b, h, (c + 2) * 128,
                        sb + AT_K0 + (c & 1) * 32768, sb + AT_K0 + (c & 1) * 32768 + 16384, tid);
            CP_COMMIT();
        }
    }

    // ---- prefetch V chunks 0,1 (overlaps softmax)
    attn_load_v(vTh, vTl, bh, 0, sb + AT_K0, sb + AT_K0 + 8192, tid);
    CP_COMMIT();
    attn_load_v(vTh, vTl, bh, 64, sb + AT_K0 + 32768, sb + AT_K0 + 40960, tid);
    CP_COMMIT();

    // ---- phase 2: softmax; write normalized P to gmem and back to sP
    for (int r = w; r < 32; r += 8) {
        float* row = &sP[r * SS];
        float m = -1e30f;
        for (int cc = lane; cc < SS; cc += 32) m = fmaxf(m, row[cc]);
        #pragma unroll
        for (int o = 16; o > 0; o >>= 1) m = fmaxf(m, __shfl_xor_sync(0xFFFFFFFFu, m, o));
        float sum = 0.f;
        for (int cc = lane; cc < SS; cc += 32) {
            float e = __expf(row[cc] - m);
            row[cc] = e;
            sum += e;
        }
        #pragma unroll
        for (int o = 16; o > 0; o >>= 1) sum += __shfl_xor_sync(0xFFFFFFFFu, sum, o);
        float inv = 1.0f / sum;
        size_t base = ((size_t)(bh * SS) + q0 + r) * SS;
        for (int cc = lane; cc < SS; cc += 32) {
            float val = row[cc] * inv;
            row[cc] = val;
            attn_out[base + cc] = val;
        }
    }

    // ---- phase 3: AV (16 chunks of 64 keys), accumulate in registers
    const int wmv = (w >> 2) * 16;
    const int wnv = (w & 3) * 16;
    float vac[2][4] = {};
    for (int c = 0; c < 16; c++) {
        if (c + 1 < 16) CP_WAIT1(); else CP_WAIT0();
        __syncthreads();   // V ready; all softmax/mma done

        // convert P chunk [32][64] -> bf16 hi/lo
        #pragma unroll
        for (int i = 0; i < 4; i++) {
            int fid = tid + i * 256;
            int row = fid >> 5;
            int pr = (fid & 31) * 2;
            float2 v = *(float2*)&sP[row * SS + c * 64 + pr];
            __nv_bfloat16 hx = __float2bfloat16(v.x);
            __nv_bfloat16 hy = __float2bfloat16(v.y);
            unsigned hp = ((unsigned)__bfloat16_as_ushort(hy) << 16) | __bfloat16_as_ushort(hx);
            __nv_bfloat16 lx = __float2bfloat16(v.x - __bfloat162float(hx));
            __nv_bfloat16 ly = __float2bfloat16(v.y - __bfloat162float(hy));
            unsigned lp = ((unsigned)__bfloat16_as_ushort(ly) << 16) | __bfloat16_as_ushort(lx);
            unsigned so = SWZ128((unsigned)(row * 128 + pr * 2));
            *(unsigned*)(smem + AT_PH + so) = hp;
            *(unsigned*)(smem + AT_PL + so) = lp;
        }
        __syncthreads();

        unsigned vbH = sb + AT_K0 + (c & 1) * 32768;
        unsigned vbL = vbH + 8192;
        #pragma unroll
        for (int p = 0; p < 3; p++) {
            unsigned aBase = sb + (p == 1 ? AT_PL : AT_PH);
            unsigned bBase = (p == 2) ? vbL : vbH;
            #pragma unroll
            for (int ks = 0; ks < 4; ks++) {
                int kb = ks * 32;
                unsigned afr[4];
                LDMX4(afr[0], afr[1], afr[2], afr[3],
                      aBase + SWZ128((unsigned)((wmv + lrow) * 128 + kb + lcol)));
                unsigned bfr[4];
                LDMX4(bfr[0], bfr[1], bfr[2], bfr[3],
                      bBase + SWZ128((unsigned)((wnv + lrow) * 128 + kb + lcol)));
                MMA16816(vac[0], afr, bfr[0], bfr[2]);
                MMA16816(vac[1], afr, bfr[1], bfr[3]);
            }
        }
        __syncthreads();
        if (c + 2 < 16) {
            unsigned nb = sb + AT_K0 + (c & 1) * 32768;
            attn_load_v(vTh, vTl, bh, (c + 2) * 64, nb, nb + 8192, tid);
            CP_COMMIT();
        }
    }

    // ---- epilogue: write values (head-interleaved) for O-proj
    {
        int r0 = wmv + (lane >> 2);
        int c0 = wnv + (lane & 3) * 2;
        #pragma unroll
        for (int j = 0; j < 2; j++) {
            int col = h * 64 + c0 + j * 8;
            *(float2*)&g_vals[(size_t)(b * SS + q0 + r0) * DD + col] = make_float2(vac[j][0], vac[j][1]);
            *(float2*)&g_vals[(size_t)(b * SS + q0 + r0 + 8) * DD + col] = make_float2(vac[j][2], vac[j][3]);
        }
    }
}

// ---------------------------------------------------------------------------
extern "C" void kernel_launch(void* const* d_in, const int* in_sizes, int n_in,
                              void* d_out, int out_size)
{
    const float* x     = (const float*)d_in[0];
    const float* W_qkv = (const float*)d_in[1];
    const float* b_qkv = (const float*)d_in[2];
    const float* W_o   = (const float*)d_in[3];
    const float* b_o   = (const float*)d_in[4];

    float* out_o    = (float*)d_out;
    float* out_attn = (float*)d_out + (size_t)BB * SS * DD;

    float *qkv_ptr, *vals_ptr;
    __nv_bfloat16 *xhi, *xlo, *wqh, *wql, *woh, *wol, *vhi, *vlo;
    __nv_bfloat16 *qhp, *qlp, *vthp, *vtlp;
    cudaGetSymbolAddress((void**)&qkv_ptr, g_qkv);
    cudaGetSymbolAddress((void**)&vals_ptr, g_vals);
    cudaGetSymbolAddress((void**)&xhi, g_xhi);
    cudaGetSymbolAddress((void**)&xlo, g_xlo);
    cudaGetSymbolAddress((void**)&wqh, g_wqT_hi);
    cudaGetSymbolAddress((void**)&wql, g_wqT_lo);
    cudaGetSymbolAddress((void**)&woh, g_woT_hi);
    cudaGetSymbolAddress((void**)&wol, g_woT_lo);
    cudaGetSymbolAddress((void**)&vhi, g_vhi);
    cudaGetSymbolAddress((void**)&vlo, g_vlo);
    cudaGetSymbolAddress((void**)&qhp, g_qh);
    cudaGetSymbolAddress((void**)&qlp, g_ql);
    cudaGetSymbolAddress((void**)&vthp, g_vTh);
    cudaGetSymbolAddress((void**)&vtlp, g_vTl);

    cudaFuncSetAttribute(gemm3x_mma, cudaFuncAttributeMaxDynamicSharedMemorySize, GT_TOTAL);
    cudaFuncSetAttribute(attn_mma, cudaFuncAttributeMaxDynamicSharedMemorySize, AT_TOTAL);

    // 0) prep: split x, transpose+split weights
    {
        int n4 = BB * SS * DD / 4;
        split_kernel<<<(n4 + 255) / 256, 256>>>(x, xhi, xlo, n4);
        dim3 g1(3 * DD / 32, DD / 32);
        tsplit_kernel<<<g1, dim3(32, 8)>>>(W_qkv, wqh, wql, DD, 3 * DD);
        dim3 g2(DD / 32, DD / 32);
        tsplit_kernel<<<g2, dim3(32, 8)>>>(W_o, woh, wol, DD, DD);
    }

    // 1) QKV projection (tensor)
    {
        dim3 grid(3 * DD / 128, BB * SS / 128);
        gemm3x_mma<<<grid, 256, GT_TOTAL>>>(xhi, xlo, wqh, wql, b_qkv, qkv_ptr,
                                            BB * SS, 3 * DD, DD);
    }

    // 2) split qkv -> bf16 hi/lo, V^T split
    {
        int n4 = BB * SS * 3 * DD / 4;
        split_kernel<<<(n4 + 255) / 256, 256>>>(qkv_ptr, qhp, qlp, n4);
        dim3 gv(SS / 32, HDIM / 32, BB * HH);
        vT_kernel<<<gv, dim3(32, 8)>>>(qkv_ptr, vthp, vtlp);
    }

    // 3) fused tensorized attention
    {
        dim3 grid(SS / 32, HH, BB);
        attn_mma<<<grid, 256, AT_TOTAL>>>(qhp, qlp, vthp, vtlp, out_attn);
    }

    // 4) split vals, O-proj (tensor)
    {
        int n4 = BB * SS * DD / 4;
        split_kernel<<<(n4 + 255) / 256, 256>>>(vals_ptr, vhi, vlo, n4);
        dim3 grid(DD / 128, BB * SS / 128);
        gemm3x_mma<<<grid, 256, GT_TOTAL>>>(vhi, vlo, woh, wol, b_o, out_o,
                                            BB * SS, DD, DD);
    }
}